// round 15
// baseline (speedup 1.0000x reference)
#include <cuda_runtime.h>
#include <cstdint>

typedef unsigned long long ull;

#define T_STEPS 512
#define BATCH   512
#define SDIM    64
#define HID     128
#define ADIM    10
#define CSZ     8
#define NCTA    128
#define NTHR    256
#define BC      32      // batch rows per cluster
#define UPC     16      // hidden units per CTA

#define WXS 68          // 64-wide weight row stride (2*WXS mod 32 == 8 -> conflict-free)
#define WHS 132         // 128-wide weight row stride (2*WHS mod 32 == 8)
#define GS  66          // gate exchange row stride
#define WOS 132
#define HBUF 4096       // one h buffer: 32 rows x 128 (swizzled, no pad)

// float-element offsets into dynamic smem
#define F_W0I 0         // 64*68   = 4352
#define F_W0H 4352      // 64*132  = 8448
#define F_W1I 12800     // 8448
#define F_W1H 21248     // 8448
#define F_H0  29696     // 2*4096  = 8192
#define F_H1  37888     // 8192
#define F_X   46080     // 32*64   = 2048
#define F_G   48128     // 32*66   = 2112
#define F_WO  50240     // 10*132  = 1320
#define F_B0  51560     // 64
#define F_B1  51624     // 64
#define F_BO  51688     // 10 + pad
#define SMEM_FLOATS 51712
#define SMEM_BYTES (SMEM_FLOATS*4)   // 206,848 B

__device__ __forceinline__ void fma2(ull &d, ull a, ull b) {
    asm("fma.rn.f32x2 %0, %1, %2, %0;" : "+l"(d) : "l"(a), "l"(b));
}
__device__ __forceinline__ float f2sum(ull a) {
    return __uint_as_float((unsigned)a) + __uint_as_float((unsigned)(a >> 32));
}
__device__ __forceinline__ ull packf2(float lo, float hi) {
    return ((ull)__float_as_uint(hi) << 32) | (ull)__float_as_uint(lo);
}
__device__ __forceinline__ float fsig(float v)  { return __fdividef(1.f, 1.f + __expf(-v)); }
__device__ __forceinline__ float ftanh(float v) { return fmaf(2.f, fsig(v + v), -1.f); }

__device__ __forceinline__ uint32_t smem_u32(const void* p) {
    uint32_t a;
    asm("{ .reg .u64 t; cvta.to.shared.u64 t, %1; cvt.u32.u64 %0, t; }" : "=r"(a) : "l"(p));
    return a;
}
__device__ __forceinline__ void st_cluster_u64(uint32_t addr, uint32_t rank, ull v) {
    uint32_t ra;
    asm volatile("mapa.shared::cluster.u32 %0, %1, %2;" : "=r"(ra) : "r"(addr), "r"(rank));
    asm volatile("st.shared::cluster.u64 [%0], %1;" :: "r"(ra), "l"(v) : "memory");
}
#define CLUSTER_ARRIVE() asm volatile("barrier.cluster.arrive.aligned;" ::: "memory")
#define CLUSTER_WAIT()   asm volatile("barrier.cluster.wait.aligned;"   ::: "memory")

// acc[2 rows][4 batch] += W[2rows][4k] * h[4batch][4k] (one float4 chunk)
__device__ __forceinline__ void mac4(ull (&acc)[2][4],
        const float* __restrict__ wa, const float* __restrict__ wb,
        const float* __restrict__ h0, int hstride, int soff)
{
    ulonglong2 A = *(const ulonglong2*)wa;
    ulonglong2 B = *(const ulonglong2*)wb;
#pragma unroll
    for (int j = 0; j < 4; j++) {
        ulonglong2 H = *(const ulonglong2*)(h0 + j*hstride + soff);
        fma2(acc[0][j], A.x, H.x); fma2(acc[0][j], A.y, H.y);
        fma2(acc[1][j], B.x, H.x); fma2(acc[1][j], B.y, H.y);
    }
}

extern __shared__ float smem[];

__global__ void __cluster_dims__(CSZ, 1, 1) __launch_bounds__(NTHR, 1)
lstm_cluster(const float* __restrict__ x,
             const float* __restrict__ Wih0, const float* __restrict__ Whh0,
             const float* __restrict__ bih0, const float* __restrict__ bhh0,
             const float* __restrict__ Wih1, const float* __restrict__ Whh1,
             const float* __restrict__ bih1, const float* __restrict__ bhh1,
             const float* __restrict__ Wout, const float* __restrict__ bout,
             float* __restrict__ out)
{
    const int tid  = threadIdx.x;
    const int rank = blockIdx.x & (CSZ - 1);
    const int cidx = blockIdx.x >> 3;

    float* sW0i = smem + F_W0I;
    float* sW0h = smem + F_W0H;
    float* sW1i = smem + F_W1I;
    float* sW1h = smem + F_W1H;
    float* sH0  = smem + F_H0;
    float* sH1  = smem + F_H1;
    float* sX   = smem + F_X;
    float* sG   = smem + F_G;
    float* sWO  = smem + F_WO;
    float* sB0  = smem + F_B0;
    float* sB1  = smem + F_B1;
    float* sBO  = smem + F_BO;

    // ----- prologue: this CTA's 64 gate rows of all 4 weight mats -> smem -----
    {
        int rr = tid >> 2, q = tid & 3;                 // 64 rows x 4 quarters
        int grow = (rr >> 4) * HID + rank * UPC + (rr & 15);
        const float4* s0 = (const float4*)(Wih0 + (size_t)grow * SDIM) + q * 4;
        float4* d0 = (float4*)(sW0i + rr * WXS) + q * 4;
#pragma unroll
        for (int i = 0; i < 4; i++) d0[i] = s0[i];
        const float4* s1 = (const float4*)(Whh0 + (size_t)grow * HID) + q * 8;
        float4* d1 = (float4*)(sW0h + rr * WHS) + q * 8;
#pragma unroll
        for (int i = 0; i < 8; i++) d1[i] = s1[i];
        const float4* s2 = (const float4*)(Wih1 + (size_t)grow * HID) + q * 8;
        float4* d2 = (float4*)(sW1i + rr * WHS) + q * 8;
#pragma unroll
        for (int i = 0; i < 8; i++) d2[i] = s2[i];
        const float4* s3 = (const float4*)(Whh1 + (size_t)grow * HID) + q * 8;
        float4* d3 = (float4*)(sW1h + rr * WHS) + q * 8;
#pragma unroll
        for (int i = 0; i < 8; i++) d3[i] = s3[i];
    }
    if (tid < 64) {
        int grow = (tid >> 4) * HID + rank * UPC + (tid & 15);
        sB0[tid] = bih0[grow] + bhh0[grow];
        sB1[tid] = bih1[grow] + bhh1[grow];
    }
    for (int i = tid; i < ADIM * HID; i += NTHR)
        sWO[(i >> 7) * WOS + (i & 127)] = Wout[i];
    if (tid < ADIM) sBO[tid] = bout[tid];
    for (int i = tid; i < 2 * HBUF; i += NTHR) { sH0[i] = 0.f; sH1[i] = 0.f; }
    __syncthreads();
    CLUSTER_ARRIVE(); CLUSTER_WAIT();   // all buffers zeroed before any peer push

    // roles: accumulation: rp = row-pair (0..31), bg = batch-group-of-4 (0..7)
    //        cell:         cb = rp (batch row), ca = bg (unit-pair)
    const int rp = tid >> 3;
    const int bg = tid & 7;

    const float* w0ia = sW0i + (2*rp)*WXS; const float* w0ib = w0ia + WXS;
    const float* w0ha = sW0h + (2*rp)*WHS; const float* w0hb = w0ha + WHS;
    const float* w1ia = sW1i + (2*rp)*WHS; const float* w1ib = w1ia + WHS;
    const float* w1ha = sW1h + (2*rp)*WHS; const float* w1hb = w1ha + WHS;

    float2 cbias0[4], cbias1[4];
#pragma unroll
    for (int g = 0; g < 4; g++) {
        cbias0[g] = *(const float2*)&sB0[g*16 + 2*bg];
        cbias1[g] = *(const float2*)&sB1[g*16 + 2*bg];
    }
    float2 c0s = {0.f, 0.f}, c1s = {0.f, 0.f};

    const uint32_t sbase = smem_u32(smem);
    const int xr = tid >> 3, xk8 = tid & 7;           // x staging role
    // x(0) prefetch
    float4 xf0, xf1;
    {
        const float4* xg = (const float4*)(x + ((size_t)(cidx*BC + xr)) * SDIM + 8*xk8);
        xf0 = __ldg(xg); xf1 = __ldg(xg + 1);
    }

    for (int t = 0; t < T_STEPS; t++) {
        const int rb = t & 1, wb = rb ^ 1;

        // ---- stage x_t (swizzled chunks), prefetch x_{t+1} ----
        {
            int sw0 = ((2*xk8     + (xr >> 2)) & 15) * 4;
            int sw1 = ((2*xk8 + 1 + (xr >> 2)) & 15) * 4;
            *(float4*)(sX + xr*SDIM + sw0) = xf0;
            *(float4*)(sX + xr*SDIM + sw1) = xf1;
        }
        __syncthreads();
        {
            int tn = (t + 1 < T_STEPS) ? t + 1 : t;
            const float4* xg = (const float4*)(x + ((size_t)tn*BATCH + cidx*BC + xr)*SDIM + 8*xk8);
            xf0 = __ldg(xg); xf1 = __ldg(xg + 1);
        }

        // ---- layer 0: gates = W0i*x + W0h*h0_old ----
        ull acc[2][4];
#pragma unroll
        for (int r = 0; r < 2; r++)
#pragma unroll
            for (int j = 0; j < 4; j++) acc[r][j] = 0ull;
        {
            const float* xrow = sX + (4*bg)*SDIM;
#pragma unroll
            for (int c = 0; c < 16; c++)
                mac4(acc, w0ia + 4*c, w0ib + 4*c, xrow, SDIM, ((c + bg) & 15) * 4);
            const float* hrow = sH0 + rb*HBUF + (4*bg)*HID;
#pragma unroll 8
            for (int c = 0; c < 32; c++)
                mac4(acc, w0ha + 4*c, w0hb + 4*c, hrow, HID, ((c + bg) & 31) * 4);
        }
#pragma unroll
        for (int j = 0; j < 4; j++) {
            float2 v; v.x = f2sum(acc[0][j]); v.y = f2sum(acc[1][j]);
            *(float2*)&sG[(4*bg + j)*GS + 2*rp] = v;
        }
        __syncthreads();

        // ---- cell 0: units (2bg, 2bg+1) of this CTA, batch row rp ----
        {
            const int cb = rp, ca = bg;
            float2 gI = *(const float2*)&sG[cb*GS +  0 + 2*ca];
            float2 gF = *(const float2*)&sG[cb*GS + 16 + 2*ca];
            float2 gG = *(const float2*)&sG[cb*GS + 32 + 2*ca];
            float2 gO = *(const float2*)&sG[cb*GS + 48 + 2*ca];
            float ii = fsig (gI.x + cbias0[0].x);
            float ff = fsig (gF.x + cbias0[1].x);
            float gg = ftanh(gG.x + cbias0[2].x);
            float oo = fsig (gO.x + cbias0[3].x);
            float cn = ff*c0s.x + ii*gg; c0s.x = cn;
            float hx = oo * ftanh(cn);
            ii = fsig (gI.y + cbias0[0].y);
            ff = fsig (gF.y + cbias0[1].y);
            gg = ftanh(gG.y + cbias0[2].y);
            oo = fsig (gO.y + cbias0[3].y);
            cn = ff*c0s.y + ii*gg; c0s.y = cn;
            float hy = oo * ftanh(cn);
            int idx = cb*HID + (((rank<<2) + (ca>>1) + (cb>>2)) & 31)*4 + (ca&1)*2;
            uint32_t a = sbase + (uint32_t)(F_H0 + wb*HBUF + idx)*4u;
            ull hv = packf2(hx, hy);
#pragma unroll
            for (int pr = 0; pr < CSZ; pr++) st_cluster_u64(a, pr, hv);
        }
        CLUSTER_ARRIVE(); CLUSTER_WAIT();   // new h0 visible everywhere

        // ---- layer 1: gates = W1i*h0_new + W1h*h1_old ----
#pragma unroll
        for (int r = 0; r < 2; r++)
#pragma unroll
            for (int j = 0; j < 4; j++) acc[r][j] = 0ull;
        {
            const float* h0row = sH0 + wb*HBUF + (4*bg)*HID;
#pragma unroll 8
            for (int c = 0; c < 32; c++)
                mac4(acc, w1ia + 4*c, w1ib + 4*c, h0row, HID, ((c + bg) & 31) * 4);
            const float* h1row = sH1 + rb*HBUF + (4*bg)*HID;
#pragma unroll 8
            for (int c = 0; c < 32; c++)
                mac4(acc, w1ha + 4*c, w1hb + 4*c, h1row, HID, ((c + bg) & 31) * 4);
        }
#pragma unroll
        for (int j = 0; j < 4; j++) {
            float2 v; v.x = f2sum(acc[0][j]); v.y = f2sum(acc[1][j]);
            *(float2*)&sG[(4*bg + j)*GS + 2*rp] = v;
        }
        __syncthreads();

        // ---- cell 1 ----
        {
            const int cb = rp, ca = bg;
            float2 gI = *(const float2*)&sG[cb*GS +  0 + 2*ca];
            float2 gF = *(const float2*)&sG[cb*GS + 16 + 2*ca];
            float2 gG = *(const float2*)&sG[cb*GS + 32 + 2*ca];
            float2 gO = *(const float2*)&sG[cb*GS + 48 + 2*ca];
            float ii = fsig (gI.x + cbias1[0].x);
            float ff = fsig (gF.x + cbias1[1].x);
            float gg = ftanh(gG.x + cbias1[2].x);
            float oo = fsig (gO.x + cbias1[3].x);
            float cn = ff*c1s.x + ii*gg; c1s.x = cn;
            float hx = oo * ftanh(cn);
            ii = fsig (gI.y + cbias1[0].y);
            ff = fsig (gF.y + cbias1[1].y);
            gg = ftanh(gG.y + cbias1[2].y);
            oo = fsig (gO.y + cbias1[3].y);
            cn = ff*c1s.y + ii*gg; c1s.y = cn;
            float hy = oo * ftanh(cn);
            int idx = cb*HID + (((rank<<2) + (ca>>1) + (cb>>2)) & 31)*4 + (ca&1)*2;
            uint32_t a = sbase + (uint32_t)(F_H1 + wb*HBUF + idx)*4u;
            ull hv = packf2(hx, hy);
#pragma unroll
            for (int pr = 0; pr < CSZ; pr++) st_cluster_u64(a, pr, hv);
        }
        CLUSTER_ARRIVE(); CLUSTER_WAIT();   // new h1 visible everywhere

        // ---- action head: 4 batch rows per CTA x 10 outputs ----
        if (tid < 4 * ADIM) {
            int rr = tid / ADIM, j = tid - rr * ADIM;
            int r = (rank << 2) + rr;
            const float* hr = sH1 + wb*HBUF + r*HID;
            const float* wo = sWO + j*WOS;
            ull a = 0ull;
#pragma unroll
            for (int c = 0; c < 32; c++) {
                ulonglong2 H = *(const ulonglong2*)(hr + ((c + rank) & 31)*4);
                ulonglong2 W = *(const ulonglong2*)(wo + 4*c);
                fma2(a, H.x, W.x); fma2(a, H.y, W.y);
            }
            out[((size_t)t*BATCH + cidx*BC + r)*ADIM + j] = ftanh(f2sum(a) + sBO[j]);
        }
        // next-step sX store is safe: head/sX reads of this step precede the
        // two cluster barriers every other CTA must pass before re-writing.
    }
}

extern "C" void kernel_launch(void* const* d_in, const int* in_sizes, int n_in,
                              void* d_out, int out_size)
{
    const float* x     = (const float*)d_in[0];
    const float* W_ih0 = (const float*)d_in[1];
    const float* W_hh0 = (const float*)d_in[2];
    const float* b_ih0 = (const float*)d_in[3];
    const float* b_hh0 = (const float*)d_in[4];
    const float* W_ih1 = (const float*)d_in[5];
    const float* W_hh1 = (const float*)d_in[6];
    const float* b_ih1 = (const float*)d_in[7];
    const float* b_hh1 = (const float*)d_in[8];
    const float* W_out = (const float*)d_in[9];
    const float* b_out = (const float*)d_in[10];
    float* out = (float*)d_out;

    cudaFuncSetAttribute(lstm_cluster, cudaFuncAttributeMaxDynamicSharedMemorySize, SMEM_BYTES);
    lstm_cluster<<<NCTA, NTHR, SMEM_BYTES>>>(x, W_ih0, W_hh0, b_ih0, b_hh0,
                                             W_ih1, W_hh1, b_ih1, b_hh1,
                                             W_out, b_out, out);
}

// round 16
// speedup vs baseline: 1.6606x; 1.6606x over previous
#include <cuda_runtime.h>
#include <cstdint>

typedef unsigned long long ull;

#define T_STEPS 512
#define BATCH   512
#define SDIM    64
#define HID     128
#define ADIM    10
#define CSZ     8
#define NCTA    128
#define NTHR    256
#define BC      32      // batch rows per cluster
#define UPC     16      // hidden units per CTA

#define WXS 68          // 64-wide weight row stride (2*WXS mod 32 == 8 -> conflict-free)
#define WHS 132         // 128-wide weight row stride (2*WHS mod 32 == 8)
#define GS  66          // gate exchange row stride
#define WOS 132
#define HBUF 4096       // one h buffer: 32 rows x 128 (swizzled, no pad)

// float-element offsets into dynamic smem
#define F_W0I 0         // 64*68   = 4352
#define F_W0H 4352      // 64*132  = 8448
#define F_W1I 12800     // 8448
#define F_W1H 21248     // 8448
#define F_H0  29696     // 2*4096  = 8192
#define F_H1  37888     // 8192
#define F_X   46080     // 32*64   = 2048
#define F_G   48128     // 32*66   = 2112
#define F_WO  50240     // 10*132  = 1320
#define F_B0  51560     // 64
#define F_B1  51624     // 64
#define F_BO  51688     // 10 + pad
#define SMEM_FLOATS 51712
#define SMEM_BYTES (SMEM_FLOATS*4)   // 206,848 B

__device__ __forceinline__ void fma2(ull &d, ull a, ull b) {
    asm("fma.rn.f32x2 %0, %1, %2, %0;" : "+l"(d) : "l"(a), "l"(b));
}
__device__ __forceinline__ float f2sum(ull a) {
    return __uint_as_float((unsigned)a) + __uint_as_float((unsigned)(a >> 32));
}
__device__ __forceinline__ ull packf2(float lo, float hi) {
    return ((ull)__float_as_uint(hi) << 32) | (ull)__float_as_uint(lo);
}
__device__ __forceinline__ float fsig(float v)  { return __fdividef(1.f, 1.f + __expf(-v)); }
__device__ __forceinline__ float ftanh(float v) { return fmaf(2.f, fsig(v + v), -1.f); }

__device__ __forceinline__ uint32_t smem_u32(const void* p) {
    uint32_t a;
    asm("{ .reg .u64 t; cvta.to.shared.u64 t, %1; cvt.u32.u64 %0, t; }" : "=r"(a) : "l"(p));
    return a;
}
__device__ __forceinline__ void st_cluster_u64(uint32_t addr, uint32_t rank, ull v) {
    uint32_t ra;
    asm volatile("mapa.shared::cluster.u32 %0, %1, %2;" : "=r"(ra) : "r"(addr), "r"(rank));
    asm volatile("st.shared::cluster.u64 [%0], %1;" :: "r"(ra), "l"(v) : "memory");
}
#define CLUSTER_ARRIVE() asm volatile("barrier.cluster.arrive.aligned;" ::: "memory")
#define CLUSTER_WAIT()   asm volatile("barrier.cluster.wait.aligned;"   ::: "memory")

// acc[2 rows][4 batch] += W[2rows][4k] * h[4batch][4k] (one float4 chunk)
__device__ __forceinline__ void mac4(ull (&acc)[2][4],
        const float* __restrict__ wa, const float* __restrict__ wb,
        const float* __restrict__ h0, int hstride, int soff)
{
    ulonglong2 A = *(const ulonglong2*)wa;
    ulonglong2 B = *(const ulonglong2*)wb;
#pragma unroll
    for (int j = 0; j < 4; j++) {
        ulonglong2 H = *(const ulonglong2*)(h0 + j*hstride + soff);
        fma2(acc[0][j], A.x, H.x); fma2(acc[0][j], A.y, H.y);
        fma2(acc[1][j], B.x, H.x); fma2(acc[1][j], B.y, H.y);
    }
}

extern __shared__ float smem[];

__global__ void __cluster_dims__(CSZ, 1, 1) __launch_bounds__(NTHR, 1)
lstm_cluster(const float* __restrict__ x,
             const float* __restrict__ Wih0, const float* __restrict__ Whh0,
             const float* __restrict__ bih0, const float* __restrict__ bhh0,
             const float* __restrict__ Wih1, const float* __restrict__ Whh1,
             const float* __restrict__ bih1, const float* __restrict__ bhh1,
             const float* __restrict__ Wout, const float* __restrict__ bout,
             float* __restrict__ out)
{
    const int tid  = threadIdx.x;
    const int rank = blockIdx.x & (CSZ - 1);
    const int cidx = blockIdx.x >> 3;

    float* sW0i = smem + F_W0I;
    float* sW0h = smem + F_W0H;
    float* sW1i = smem + F_W1I;
    float* sW1h = smem + F_W1H;
    float* sH0  = smem + F_H0;
    float* sH1  = smem + F_H1;
    float* sX   = smem + F_X;
    float* sG   = smem + F_G;
    float* sWO  = smem + F_WO;
    float* sB0  = smem + F_B0;
    float* sB1  = smem + F_B1;
    float* sBO  = smem + F_BO;

    // ----- prologue: this CTA's 64 gate rows of all 4 weight mats -> smem -----
    {
        int rr = tid >> 2, q = tid & 3;                 // 64 rows x 4 quarters
        int grow = (rr >> 4) * HID + rank * UPC + (rr & 15);
        const float4* s0 = (const float4*)(Wih0 + (size_t)grow * SDIM) + q * 4;
        float4* d0 = (float4*)(sW0i + rr * WXS) + q * 4;
#pragma unroll
        for (int i = 0; i < 4; i++) d0[i] = s0[i];
        const float4* s1 = (const float4*)(Whh0 + (size_t)grow * HID) + q * 8;
        float4* d1 = (float4*)(sW0h + rr * WHS) + q * 8;
#pragma unroll
        for (int i = 0; i < 8; i++) d1[i] = s1[i];
        const float4* s2 = (const float4*)(Wih1 + (size_t)grow * HID) + q * 8;
        float4* d2 = (float4*)(sW1i + rr * WHS) + q * 8;
#pragma unroll
        for (int i = 0; i < 8; i++) d2[i] = s2[i];
        const float4* s3 = (const float4*)(Whh1 + (size_t)grow * HID) + q * 8;
        float4* d3 = (float4*)(sW1h + rr * WHS) + q * 8;
#pragma unroll
        for (int i = 0; i < 8; i++) d3[i] = s3[i];
    }
    if (tid < 64) {
        int grow = (tid >> 4) * HID + rank * UPC + (tid & 15);
        sB0[tid] = bih0[grow] + bhh0[grow];
        sB1[tid] = bih1[grow] + bhh1[grow];
    }
    for (int i = tid; i < ADIM * HID; i += NTHR)
        sWO[(i >> 7) * WOS + (i & 127)] = Wout[i];
    if (tid < ADIM) sBO[tid] = bout[tid];
    for (int i = tid; i < 2 * HBUF; i += NTHR) { sH0[i] = 0.f; sH1[i] = 0.f; }
    __syncthreads();
    CLUSTER_ARRIVE(); CLUSTER_WAIT();   // all buffers zeroed before any peer push

    // roles: accumulation: rp = row-pair (0..31), bg = batch-group-of-4 (0..7)
    //        cell:         cb = rp (batch row), ca = bg (unit-pair)
    const int rp = tid >> 3;
    const int bg = tid & 7;

    const float* w0ia = sW0i + (2*rp)*WXS; const float* w0ib = w0ia + WXS;
    const float* w0ha = sW0h + (2*rp)*WHS; const float* w0hb = w0ha + WHS;
    const float* w1ia = sW1i + (2*rp)*WHS; const float* w1ib = w1ia + WHS;
    const float* w1ha = sW1h + (2*rp)*WHS; const float* w1hb = w1ha + WHS;

    float2 cbias0[4], cbias1[4];
#pragma unroll
    for (int g = 0; g < 4; g++) {
        cbias0[g] = *(const float2*)&sB0[g*16 + 2*bg];
        cbias1[g] = *(const float2*)&sB1[g*16 + 2*bg];
    }
    float2 c0s = {0.f, 0.f}, c1s = {0.f, 0.f};

    const uint32_t sbase = smem_u32(smem);
    const int xr = tid >> 3, xk8 = tid & 7;           // x staging role
    // x(0) prefetch
    float4 xf0, xf1;
    {
        const float4* xg = (const float4*)(x + ((size_t)(cidx*BC + xr)) * SDIM + 8*xk8);
        xf0 = __ldg(xg); xf1 = __ldg(xg + 1);
    }

    for (int t = 0; t < T_STEPS; t++) {
        const int rb = t & 1, wb = rb ^ 1;

        // ---- stage x_t (swizzled chunks), prefetch x_{t+1} ----
        {
            int sw0 = ((2*xk8     + (xr >> 2)) & 15) * 4;
            int sw1 = ((2*xk8 + 1 + (xr >> 2)) & 15) * 4;
            *(float4*)(sX + xr*SDIM + sw0) = xf0;
            *(float4*)(sX + xr*SDIM + sw1) = xf1;
        }
        __syncthreads();
        {
            int tn = (t + 1 < T_STEPS) ? t + 1 : t;
            const float4* xg = (const float4*)(x + ((size_t)tn*BATCH + cidx*BC + xr)*SDIM + 8*xk8);
            xf0 = __ldg(xg); xf1 = __ldg(xg + 1);
        }

        // ---- layer 0: gates = W0i*x + W0h*h0_old ----
        ull acc[2][4];
#pragma unroll
        for (int r = 0; r < 2; r++)
#pragma unroll
            for (int j = 0; j < 4; j++) acc[r][j] = 0ull;
        {
            const float* xrow = sX + (4*bg)*SDIM;
#pragma unroll
            for (int c = 0; c < 16; c++)
                mac4(acc, w0ia + 4*c, w0ib + 4*c, xrow, SDIM, ((c + bg) & 15) * 4);
            const float* hrow = sH0 + rb*HBUF + (4*bg)*HID;
#pragma unroll 8
            for (int c = 0; c < 32; c++)
                mac4(acc, w0ha + 4*c, w0hb + 4*c, hrow, HID, ((c + bg) & 31) * 4);
        }
#pragma unroll
        for (int j = 0; j < 4; j++) {
            float2 v; v.x = f2sum(acc[0][j]); v.y = f2sum(acc[1][j]);
            *(float2*)&sG[(4*bg + j)*GS + 2*rp] = v;
        }
        __syncthreads();

        // ---- cell 0: units (2bg, 2bg+1) of this CTA, batch row rp ----
        {
            const int cb = rp, ca = bg;
            float2 gI = *(const float2*)&sG[cb*GS +  0 + 2*ca];
            float2 gF = *(const float2*)&sG[cb*GS + 16 + 2*ca];
            float2 gG = *(const float2*)&sG[cb*GS + 32 + 2*ca];
            float2 gO = *(const float2*)&sG[cb*GS + 48 + 2*ca];
            float ii = fsig (gI.x + cbias0[0].x);
            float ff = fsig (gF.x + cbias0[1].x);
            float gg = ftanh(gG.x + cbias0[2].x);
            float oo = fsig (gO.x + cbias0[3].x);
            float cn = ff*c0s.x + ii*gg; c0s.x = cn;
            float hx = oo * ftanh(cn);
            ii = fsig (gI.y + cbias0[0].y);
            ff = fsig (gF.y + cbias0[1].y);
            gg = ftanh(gG.y + cbias0[2].y);
            oo = fsig (gO.y + cbias0[3].y);
            cn = ff*c0s.y + ii*gg; c0s.y = cn;
            float hy = oo * ftanh(cn);
            int idx = cb*HID + (((rank<<2) + (ca>>1) + (cb>>2)) & 31)*4 + (ca&1)*2;
            uint32_t a = sbase + (uint32_t)(F_H0 + wb*HBUF + idx)*4u;
            ull hv = packf2(hx, hy);
#pragma unroll
            for (int pr = 0; pr < CSZ; pr++) st_cluster_u64(a, pr, hv);
        }
        CLUSTER_ARRIVE();                   // b1: h0_new pushed

        // ---- layer 1a (hides b1): W1h * h1_old — local buffer, no peer writes
        //      possible until every CTA passes b1 (their pushes then target the
        //      OTHER h1 buffer). sG untouched here.
#pragma unroll
        for (int r = 0; r < 2; r++)
#pragma unroll
            for (int j = 0; j < 4; j++) acc[r][j] = 0ull;
        {
            const float* h1row = sH1 + rb*HBUF + (4*bg)*HID;
#pragma unroll 8
            for (int c = 0; c < 32; c++)
                mac4(acc, w1ha + 4*c, w1hb + 4*c, h1row, HID, ((c + bg) & 31) * 4);
        }
        CLUSTER_WAIT();                     // b1 done: h0_new visible; all cell-0
                                            // sG reads cluster-wide complete.

        // ---- layer 1b: += W1i * h0_new; then exchange gates ----
        {
            const float* h0row = sH0 + wb*HBUF + (4*bg)*HID;
#pragma unroll 8
            for (int c = 0; c < 32; c++)
                mac4(acc, w1ia + 4*c, w1ib + 4*c, h0row, HID, ((c + bg) & 31) * 4);
        }
#pragma unroll
        for (int j = 0; j < 4; j++) {
            float2 v; v.x = f2sum(acc[0][j]); v.y = f2sum(acc[1][j]);
            *(float2*)&sG[(4*bg + j)*GS + 2*rp] = v;
        }
        __syncthreads();

        // ---- cell 1 ----
        {
            const int cb = rp, ca = bg;
            float2 gI = *(const float2*)&sG[cb*GS +  0 + 2*ca];
            float2 gF = *(const float2*)&sG[cb*GS + 16 + 2*ca];
            float2 gG = *(const float2*)&sG[cb*GS + 32 + 2*ca];
            float2 gO = *(const float2*)&sG[cb*GS + 48 + 2*ca];
            float ii = fsig (gI.x + cbias1[0].x);
            float ff = fsig (gF.x + cbias1[1].x);
            float gg = ftanh(gG.x + cbias1[2].x);
            float oo = fsig (gO.x + cbias1[3].x);
            float cn = ff*c1s.x + ii*gg; c1s.x = cn;
            float hx = oo * ftanh(cn);
            ii = fsig (gI.y + cbias1[0].y);
            ff = fsig (gF.y + cbias1[1].y);
            gg = ftanh(gG.y + cbias1[2].y);
            oo = fsig (gO.y + cbias1[3].y);
            cn = ff*c1s.y + ii*gg; c1s.y = cn;
            float hy = oo * ftanh(cn);
            int idx = cb*HID + (((rank<<2) + (ca>>1) + (cb>>2)) & 31)*4 + (ca&1)*2;
            uint32_t a = sbase + (uint32_t)(F_H1 + wb*HBUF + idx)*4u;
            ull hv = packf2(hx, hy);
#pragma unroll
            for (int pr = 0; pr < CSZ; pr++) st_cluster_u64(a, pr, hv);
        }
        CLUSTER_ARRIVE(); CLUSTER_WAIT();   // new h1 visible everywhere

        // ---- action head: 4 batch rows per CTA x 10 outputs ----
        if (tid < 4 * ADIM) {
            int rr = tid / ADIM, j = tid - rr * ADIM;
            int r = (rank << 2) + rr;
            const float* hr = sH1 + wb*HBUF + r*HID;
            const float* wo = sWO + j*WOS;
            ull a = 0ull;
#pragma unroll
            for (int c = 0; c < 32; c++) {
                ulonglong2 H = *(const ulonglong2*)(hr + ((c + rank) & 31)*4);
                ulonglong2 W = *(const ulonglong2*)(wo + 4*c);
                fma2(a, H.x, W.x); fma2(a, H.y, W.y);
            }
            out[((size_t)t*BATCH + cidx*BC + r)*ADIM + j] = ftanh(f2sum(a) + sBO[j]);
        }
        // next-step sX store is safe: head/sX reads of this step precede the
        // cluster barriers every other CTA must pass before re-writing.
    }
}

extern "C" void kernel_launch(void* const* d_in, const int* in_sizes, int n_in,
                              void* d_out, int out_size)
{
    const float* x     = (const float*)d_in[0];
    const float* W_ih0 = (const float*)d_in[1];
    const float* W_hh0 = (const float*)d_in[2];
    const float* b_ih0 = (const float*)d_in[3];
    const float* b_hh0 = (const float*)d_in[4];
    const float* W_ih1 = (const float*)d_in[5];
    const float* W_hh1 = (const float*)d_in[6];
    const float* b_ih1 = (const float*)d_in[7];
    const float* b_hh1 = (const float*)d_in[8];
    const float* W_out = (const float*)d_in[9];
    const float* b_out = (const float*)d_in[10];
    float* out = (float*)d_out;

    cudaFuncSetAttribute(lstm_cluster, cudaFuncAttributeMaxDynamicSharedMemorySize, SMEM_BYTES);
    lstm_cluster<<<NCTA, NTHR, SMEM_BYTES>>>(x, W_ih0, W_hh0, b_ih0, b_hh0,
                                             W_ih1, W_hh1, b_ih1, b_hh1,
                                             W_out, b_out, out);
}